// round 1
// baseline (speedup 1.0000x reference)
#include <cuda_runtime.h>

#define NB 524288
#define T_OBS 8
#define T_PRE 12
#define HH 8
#define EE 16

typedef unsigned long long ull;

// Duplicated (w,w) packed weights, pre-scaled by -log2e (gate g: -2*log2e)
struct __align__(16) Wpack {
    float2 W[2][8][8][4];   // [phase][j][k][gate]
    float2 A[2][8][2][4];   // [phase][j][m][gate]   (A = W_ih @ W_in, folded)
    float2 Bz[2][8][4];     // [phase][j][gate]      (b_ih + b_hh + W_ih@b_in, folded)
};
__device__ Wpack gPack;

// ---------------- prep: fold embedding into gate weights, scale, duplicate ----------------
__global__ void prep_kernel(
    const float* __restrict__ W_in, const float* __restrict__ b_in,
    const float* __restrict__ Wih_o, const float* __restrict__ Whh_o,
    const float* __restrict__ bih_o, const float* __restrict__ bhh_o,
    const float* __restrict__ Wih_p, const float* __restrict__ Whh_p,
    const float* __restrict__ bih_p, const float* __restrict__ bhh_p)
{
    int t = threadIdx.x;
    if (t >= 64) return;
    int ph = t >> 5, r = t & 31;
    const float* Wih = ph ? Wih_p : Wih_o;
    const float* Whh = ph ? Whh_p : Whh_o;
    const float* bih = ph ? bih_p : bih_o;
    const float* bhh = ph ? bhh_p : bhh_o;
    int g = r >> 3, j = r & 7;                       // rows: i(0-7) f(8-15) g(16-23) o(24-31)
    const float L2E = 1.4426950408889634f;
    float sc = (g == 2) ? (-2.0f * L2E) : (-L2E);    // fold sigmoid/tanh arg scaling into weights
    float a0 = 0.f, a1 = 0.f, bb = bih[r] + bhh[r];
    for (int e = 0; e < EE; e++) {
        float w = Wih[r * EE + e];
        a0 += w * W_in[e * 2 + 0];
        a1 += w * W_in[e * 2 + 1];
        bb += w * b_in[e];
    }
    a0 *= sc; a1 *= sc; bb *= sc;
    gPack.A[ph][j][0][g] = make_float2(a0, a0);
    gPack.A[ph][j][1][g] = make_float2(a1, a1);
    gPack.Bz[ph][j][g]   = make_float2(bb, bb);
    for (int k = 0; k < HH; k++) {
        float w = Whh[r * HH + k] * sc;
        gPack.W[ph][j][k][g] = make_float2(w, w);
    }
}

// ---------------- packed f32x2 helpers ----------------
__device__ __forceinline__ ull fma2(ull a, ull b, ull c) {
    ull d; asm("fma.rn.f32x2 %0, %1, %2, %3;" : "=l"(d) : "l"(a), "l"(b), "l"(c)); return d;
}
__device__ __forceinline__ ull mul2(ull a, ull b) {
    ull d; asm("mul.rn.f32x2 %0, %1, %2;" : "=l"(d) : "l"(a), "l"(b)); return d;
}
__device__ __forceinline__ ull add2(ull a, ull b) {
    ull d; asm("add.rn.f32x2 %0, %1, %2;" : "=l"(d) : "l"(a), "l"(b)); return d;
}
__device__ __forceinline__ ull pk(float lo, float hi) {
    ull d; asm("mov.b64 %0, {%1, %2};" : "=l"(d) : "f"(lo), "f"(hi)); return d;
}
__device__ __forceinline__ ull ex2_2(ull a) {   // elementwise 2^x on packed pair
    float lo, hi; asm("mov.b64 {%0, %1}, %2;" : "=f"(lo), "=f"(hi) : "l"(a));
    float el, eh;
    asm("ex2.approx.f32 %0, %1;" : "=f"(el) : "f"(lo));
    asm("ex2.approx.f32 %0, %1;" : "=f"(eh) : "f"(hi));
    return pk(el, eh);
}
__device__ __forceinline__ ull rcp2(ull a) {    // elementwise 1/x on packed pair
    float lo, hi; asm("mov.b64 {%0, %1}, %2;" : "=f"(lo), "=f"(hi) : "l"(a));
    float el, eh;
    asm("rcp.approx.f32 %0, %1;" : "=f"(el) : "f"(lo));
    asm("rcp.approx.f32 %0, %1;" : "=f"(eh) : "f"(hi));
    return pk(el, eh);
}

// One LSTM unit update for a packed pair. acc[] already hold -log2e * preact
// (gate g: -2log2e * preact), so E = ex2(acc) = exp(-x) directly.
// Four sigmoids share one reciprocal: s = 1/(1+E) via product-of-denominators.
__device__ __forceinline__ void lstm_unit(const ull acc[4], ull& c, ull& hout,
                                          ull CN2L2E, ull CONE, ull CTWO, ull CNONE)
{
    ull Ei = ex2_2(acc[0]);
    ull Ef = ex2_2(acc[1]);
    ull Eg = ex2_2(acc[2]);             // e^{-2g}
    ull Eo = ex2_2(acc[3]);
    ull Ai = add2(Ei, CONE), Bf = add2(Ef, CONE);
    ull Cg = add2(Eg, CONE), Do = add2(Eo, CONE);
    ull t1 = mul2(Ai, Bf), t2 = mul2(Cg, Do);
    ull r  = rcp2(mul2(t1, t2));
    ull q1 = mul2(r, t2), q2 = mul2(r, t1);
    ull si = mul2(q1, Bf);              // 1/(1+Ei) = sigmoid(i)
    ull sf = mul2(q1, Ai);              // sigmoid(f)
    ull sg = mul2(q2, Do);              // sigmoid(2g)
    ull so = mul2(q2, Cg);              // sigmoid(o)
    ull tg = fma2(sg, CTWO, CNONE);     // tanh(g) = 2*sigmoid(2g) - 1
    c = fma2(sf, c, mul2(si, tg));      // c' = sig(f)*c + sig(i)*tanh(g)
    ull Ec = ex2_2(mul2(c, CN2L2E));    // e^{-2c}
    ull rc = rcp2(add2(Ec, CONE));      // sigmoid(2c)
    ull tc = fma2(rc, CTWO, CNONE);     // tanh(c)
    hout = mul2(so, tc);
}

// Load 4 consecutive rows of a [B,8] tensor and pack into 2 pairs x 8 features
__device__ __forceinline__ void load_pack_state(const float* __restrict__ base, int e0, ull p[2][8])
{
    const float4* q = (const float4*)(base + (size_t)e0 * 8);
    float4 a0 = q[0], a1 = q[1];   // row e0
    float4 b0 = q[2], b1 = q[3];   // row e0+1
    float4 c0 = q[4], c1 = q[5];   // row e0+2
    float4 d0 = q[6], d1 = q[7];   // row e0+3
    p[0][0] = pk(a0.x, b0.x); p[0][1] = pk(a0.y, b0.y); p[0][2] = pk(a0.z, b0.z); p[0][3] = pk(a0.w, b0.w);
    p[0][4] = pk(a1.x, b1.x); p[0][5] = pk(a1.y, b1.y); p[0][6] = pk(a1.z, b1.z); p[0][7] = pk(a1.w, b1.w);
    p[1][0] = pk(c0.x, d0.x); p[1][1] = pk(c0.y, d0.y); p[1][2] = pk(c0.z, d0.z); p[1][3] = pk(c0.w, d0.w);
    p[1][4] = pk(c1.x, d1.x); p[1][5] = pk(c1.y, d1.y); p[1][6] = pk(c1.z, d1.z); p[1][7] = pk(c1.w, d1.w);
}

// out[a*B + b] = h[b][a]  (the transpose().reshape in the reference) — coalesced STG.128
__device__ __forceinline__ void store_h(float* __restrict__ out, int e0, ull hp[2][8])
{
    #pragma unroll
    for (int a = 0; a < 8; a++) {
        ulonglong2 v; v.x = hp[0][a]; v.y = hp[1][a];
        *(ulonglong2*)(out + (size_t)a * NB + e0) = v;
    }
}

template<int TSTEPS, int PH>
__device__ __forceinline__ void run_phase(const Wpack& sP,
    const float* __restrict__ xbase, int e0,
    ull hp[2][8], ull cp[2][8],
    ull CN2L2E, ull CONE, ull CTWO, ull CNONE)
{
    const float4* xp = (const float4*)(xbase + (size_t)e0 * 2);
    const size_t S4 = (size_t)NB * 2 / 4;   // float4 stride per timestep
    float4 xA = xp[0], xB = xp[1];          // prefetch t=0

    #pragma unroll 1
    for (int t = 0; t < TSTEPS; t++) {
        ull px0[2], px1[2];
        px0[0] = pk(xA.x, xA.z); px0[1] = pk(xA.y, xA.w);   // pair0: elems e0,e0+1
        px1[0] = pk(xB.x, xB.z); px1[1] = pk(xB.y, xB.w);   // pair1: elems e0+2,e0+3
        if (t + 1 < TSTEPS) { xA = xp[(size_t)(t + 1) * S4]; xB = xp[(size_t)(t + 1) * S4 + 1]; }

        ull hn[2][8];
        #pragma unroll
        for (int j = 0; j < 8; j++) {
            ull acc0[4], acc1[4];
            {
                const ulonglong2* bz = (const ulonglong2*)&sP.Bz[PH][j][0];
                ulonglong2 b01 = bz[0], b23 = bz[1];
                acc0[0] = b01.x; acc0[1] = b01.y; acc0[2] = b23.x; acc0[3] = b23.y;
                acc1[0] = b01.x; acc1[1] = b01.y; acc1[2] = b23.x; acc1[3] = b23.y;
            }
            #pragma unroll
            for (int m = 0; m < 2; m++) {
                const ulonglong2* aw = (const ulonglong2*)&sP.A[PH][j][m][0];
                ulonglong2 w01 = aw[0], w23 = aw[1];
                acc0[0] = fma2(w01.x, px0[m], acc0[0]); acc1[0] = fma2(w01.x, px1[m], acc1[0]);
                acc0[1] = fma2(w01.y, px0[m], acc0[1]); acc1[1] = fma2(w01.y, px1[m], acc1[1]);
                acc0[2] = fma2(w23.x, px0[m], acc0[2]); acc1[2] = fma2(w23.x, px1[m], acc1[2]);
                acc0[3] = fma2(w23.y, px0[m], acc0[3]); acc1[3] = fma2(w23.y, px1[m], acc1[3]);
            }
            #pragma unroll
            for (int k = 0; k < 8; k++) {
                const ulonglong2* ww = (const ulonglong2*)&sP.W[PH][j][k][0];
                ulonglong2 w01 = ww[0], w23 = ww[1];
                ull hk0 = hp[0][k], hk1 = hp[1][k];
                acc0[0] = fma2(w01.x, hk0, acc0[0]); acc1[0] = fma2(w01.x, hk1, acc1[0]);
                acc0[1] = fma2(w01.y, hk0, acc0[1]); acc1[1] = fma2(w01.y, hk1, acc1[1]);
                acc0[2] = fma2(w23.x, hk0, acc0[2]); acc1[2] = fma2(w23.x, hk1, acc1[2]);
                acc0[3] = fma2(w23.y, hk0, acc0[3]); acc1[3] = fma2(w23.y, hk1, acc1[3]);
            }
            lstm_unit(acc0, cp[0][j], hn[0][j], CN2L2E, CONE, CTWO, CNONE);
            lstm_unit(acc1, cp[1][j], hn[1][j], CN2L2E, CONE, CTWO, CNONE);
        }
        #pragma unroll
        for (int j = 0; j < 8; j++) { hp[0][j] = hn[0][j]; hp[1][j] = hn[1][j]; }
    }
}

__global__ void __launch_bounds__(128, 2)
enc_kernel(const float* __restrict__ obs, const float* __restrict__ pre,
           const float* __restrict__ h0, const float* __restrict__ c0,
           const float* __restrict__ c0p, float* __restrict__ out)
{
    __shared__ Wpack sP;
    {
        const float2* src = (const float2*)&gPack;
        float2* dst = (float2*)&sP;
        #pragma unroll 2
        for (int i = threadIdx.x; i < (int)(sizeof(Wpack) / sizeof(float2)); i += 128)
            dst[i] = src[i];
    }
    __syncthreads();

    const int tid = blockIdx.x * 128 + threadIdx.x;
    const int e0 = tid * 4;

    const ull CN2L2E = pk(-2.8853900817779268f, -2.8853900817779268f);
    const ull CONE   = pk(1.0f, 1.0f);
    const ull CTWO   = pk(2.0f, 2.0f);
    const ull CNONE  = pk(-1.0f, -1.0f);

    ull hp[2][8], cp[2][8];
    load_pack_state(h0, e0, hp);
    load_pack_state(c0, e0, cp);

    run_phase<T_OBS, 0>(sP, obs, e0, hp, cp, CN2L2E, CONE, CTWO, CNONE);
    store_h(out, e0, hp);                    // c_out = transpose(h_obs)

    load_pack_state(c0p, e0, cp);            // cell state re-init; h carries over
    run_phase<T_PRE, 1>(sP, pre, e0, hp, cp, CN2L2E, CONE, CTWO, CNONE);
    store_h(out + (size_t)NB * 8, e0, hp);   // x_out = transpose(h_pre)
}

extern "C" void kernel_launch(void* const* d_in, const int* in_sizes, int n_in,
                              void* d_out, int out_size)
{
    const float* obs   = (const float*)d_in[0];
    const float* pre   = (const float*)d_in[1];
    const float* h0    = (const float*)d_in[2];
    const float* c0    = (const float*)d_in[3];
    const float* c0p   = (const float*)d_in[4];
    const float* W_in  = (const float*)d_in[5];
    const float* b_in  = (const float*)d_in[6];
    const float* Wih_o = (const float*)d_in[7];
    const float* Whh_o = (const float*)d_in[8];
    const float* bih_o = (const float*)d_in[9];
    const float* bhh_o = (const float*)d_in[10];
    const float* Wih_p = (const float*)d_in[11];
    const float* Whh_p = (const float*)d_in[12];
    const float* bih_p = (const float*)d_in[13];
    const float* bhh_p = (const float*)d_in[14];

    prep_kernel<<<1, 64>>>(W_in, b_in, Wih_o, Whh_o, bih_o, bhh_o,
                           Wih_p, Whh_p, bih_p, bhh_p);
    enc_kernel<<<NB / 4 / 128, 128>>>(obs, pre, h0, c0, c0p, (float*)d_out);
}